// round 8
// baseline (speedup 1.0000x reference)
#include <cuda_runtime.h>
#include <math_constants.h>

// ---------------------------------------------------------------------------
// MultiTaskLossWrapper — single launch, one *hidden* grid barrier.
// Schedule per block:
//   1. produce exp() for its own 32 elements into g_sp, arrive at barrier
//   2. build the 4 pair lists locally (age/grade/h3 only — no exp needed)
//   3. run its share of pair-rank units           (hides the barrier wait)
//   4. wait barrier (already flipped), stage g_sp -> smem, Cox sweep
//   5. last block (atomic ticket) combines all partials in fixed order
// No fp atomics; fully deterministic; replay-safe (phase monotone, ticket
// and arrive counter self-reset).
// Inputs: 0 hazard3d f32[B], 1 hazard1d f32[B], 2 survtime f32[B],
//         3 censor f32[B], 4 vars_ f32[4], 5 beta1, 6 beta2,
//         7 age i32[B], 8 grade i32[B].  Output: f32[1]
// ---------------------------------------------------------------------------

#define G 128
#define T 512
#define NW 16
#define TOTW (G * NW)
#define BMAX 4096
#define EPB 32
#define NK 8                   // elems per thread for list building
#define LISTPAD (BMAX + 128)

__constant__ float c_risk_table[9] = {1.0f, 1.0f, 0.91f, 1.12f, 1.71f,
                                      2.41f, 3.27f, 5.18f, 8.44f};

__device__ float4 g_sp[BMAX];          // (surv, exp(h3), exp(h1), censor)
__device__ float2 g_coxp[G];
__device__ float4 g_pairp[G];
__device__ int               g_arr = 0;       // barrier arrive counter
__device__ volatile unsigned g_phase = 0;     // monotone across replays
__device__ int               g_ticket = 0;    // finisher resets

__device__ __forceinline__ float warpSumF(float v) {
#pragma unroll
    for (int o = 16; o; o >>= 1) v += __shfl_xor_sync(0xffffffffu, v, o);
    return v;
}

__global__ void __launch_bounds__(T)
fused_kernel(const float* __restrict__ h3, const float* __restrict__ h1,
             const float* __restrict__ surv, const float* __restrict__ cen,
             const float* __restrict__ vars,
             const float* __restrict__ b1p, const float* __restrict__ b2p,
             const int* __restrict__ age, const int* __restrict__ grade,
             float* __restrict__ out, int B) {
    extern __shared__ float sm[];
    float*  s_surv  = sm;                                  // [BMAX]
    float2* s_e     = (float2*)(sm + BMAX);                // [BMAX]
    int*    s_lmeta = (int*)(sm + 3 * BMAX);               // [LISTPAD]
    float*  s_lh    = (float*)(sm + 3 * BMAX + LISTPAD);   // [LISTPAD]

    __shared__ int      s_gc[4][G];
    __shared__ int      s_tot[4], s_off[5];
    __shared__ float    tabL[81], tabH[81];
    __shared__ float    s_p3[EPB][4], s_p1[EPB][4];
    __shared__ float    s_pr[4][NW];
    __shared__ float    s_fin[6][4];
    __shared__ unsigned s_ph;
    __shared__ int      s_last;

    const int b = blockIdx.x, tid = threadIdx.x;
    const int w = tid >> 5, lane = tid & 31;

    if (tid == 0) s_ph = g_phase;    // capture barrier phase before any arrive

    // ---- 1. produce our 32 elements of g_sp, arrive (non-blocking) --------
    if (w == 0) {
        int e = b * EPB + lane;
        if (e < B) {
            g_sp[e] = make_float4(surv[e], __expf(h3[e]), __expf(h1[e]), cen[e]);
        }
        __syncwarp();
        if (lane == 0) {
            __threadfence();
            unsigned ph = s_ph;
            if (atomicAdd(&g_arr, 1) == G - 1) {
                g_arr = 0;
                __threadfence();
                g_phase = ph + 1;
            }
        }
    } else if (tid >= 32 && tid < 194) {
        // alpha tables
        int q = tid - 32;
        bool isL = q < 81;
        int i = isL ? q : q - 81;
        float bb = isL ? *b1p : *b2p;
        float d = (c_risk_table[i % 9] - c_risk_table[i / 9]) * 0.125f;
        float al = __fdividef(d, 1.0f + __expf(-bb * d));
        if (isL) tabL[i] = al; else tabH[i] = al;
    }

    // ---- 2. build pair lists locally (no exp involved) --------------------
    unsigned mlpack = 0u, bkpack = 0u;
    float hv[NK];
    {
        int a8[NK], g8[NK];
#pragma unroll
        for (int k = 0; k < NK; k++) {
            int e = w * (NK * 32) + k * 32 + lane;
            bool valid = (e < B);
            a8[k] = valid ? age[e]   : -1;
            g8[k] = valid ? grade[e] : -1;
            hv[k] = valid ? h3[e]    : 0.0f;
        }
#pragma unroll
        for (int k = 0; k < NK; k++) {
            int a_ = a8[k], g_ = g8[k];
            int ml = -1;
            if (g_ == 0)                 ml = (a_ < 40) ? 0 : 1;
            else if (g_ == 1 || g_ == 2) ml = (a_ < 65) ? 2 : 3;
            int bkt = a_ / 10; bkt = bkt < 0 ? 0 : (bkt > 8 ? 8 : bkt);
            mlpack |= (unsigned)(ml + 1) << (3 * k);
            bkpack |= (unsigned)bkt << (4 * k);
#pragma unroll
            for (int l = 0; l < 4; l++) {
                unsigned mk = __ballot_sync(0xffffffffu, ml == l);
                if (lane == 0) s_gc[l][w * NK + k] = __popc(mk);
            }
        }
    }
    __syncthreads();

    if (w < 4) {     // warp l: exclusive scan of 128 group counts
        int l = w;
        int g0 = lane * 4;
        int v0 = s_gc[l][g0], v1 = s_gc[l][g0 + 1];
        int v2 = s_gc[l][g0 + 2], v3 = s_gc[l][g0 + 3];
        int ls = v0 + v1 + v2 + v3;
        int x = ls;
#pragma unroll
        for (int o = 1; o < 32; o <<= 1) {
            int y = __shfl_up_sync(0xffffffffu, x, o);
            if (lane >= o) x += y;
        }
        int base = x - ls;
        s_gc[l][g0]     = base;
        s_gc[l][g0 + 1] = base + v0;
        s_gc[l][g0 + 2] = base + v0 + v1;
        s_gc[l][g0 + 3] = base + v0 + v1 + v2;
        if (lane == 31) s_tot[l] = x;
    }
    __syncthreads();
    if (tid == 0) {
        int o = 0;
#pragma unroll
        for (int l = 0; l < 4; l++) { s_off[l] = o; o += (s_tot[l] + 31) & ~31; }
        s_off[4] = o;
    }
    __syncthreads();

#pragma unroll
    for (int k = 0; k < NK; k++) {
        int ml = (int)((mlpack >> (3 * k)) & 7u) - 1;
        unsigned mymask = 0u;
#pragma unroll
        for (int l = 0; l < 4; l++) {
            unsigned mk = __ballot_sync(0xffffffffu, ml == l);
            if (ml == l) mymask = mk;
        }
        if (ml >= 0) {
            int e = w * (NK * 32) + k * 32 + lane;
            int bkt = (int)((bkpack >> (4 * k)) & 15u);
            int pos = s_off[ml] + s_gc[ml][w * NK + k]
                    + __popc(mymask & ((1u << lane) - 1u));
            s_lmeta[pos] = (e << 4) | bkt;
            s_lh[pos] = hv[k];
        }
    }
#pragma unroll
    for (int l = 0; l < 4; l++) {
        int sent = (l == 0 || l == 2) ? 0x7FFFFFF0 : -16;
        for (int i = s_off[l] + s_tot[l] + tid; i < s_off[l + 1]; i += T) {
            s_lmeta[i] = sent; s_lh[i] = 0.0f;
        }
    }
    __syncthreads();   // lists + tables complete

    // ---- 3. pair phase (hides the barrier wait) ---------------------------
    {
        const int n0 = s_tot[0], n1 = s_tot[1], n2 = s_tot[2], n3 = s_tot[3];
        const int uL = (n0 + 31) >> 5, vL = (n1 + 31) >> 5;
        const int uH = (n2 + 31) >> 5, vH = (n3 + 31) >> 5;
        const int NTL = uL * vL, NT = NTL + uH * vH;
        float aS0 = 0.f, aC0 = 0.f, aS1 = 0.f, aC1 = 0.f;
        const int gw = b * NW + w;

        for (int t = gw; t < NT; t += TOTW) {
            int prob, lu, hvv, lo, ho, nHigh;
            const float* tab;
            if (t < NTL) {
                prob = 0; lu = t / vL; hvv = t - lu * vL;
                lo = s_off[0]; ho = s_off[1]; nHigh = n1; tab = tabL;
            } else {
                int tt = t - NTL;
                prob = 1; lu = tt / vH; hvv = tt - lu * vH;
                lo = s_off[2]; ho = s_off[3]; nHigh = n3; tab = tabH;
            }
            int lowMin = s_lmeta[lo + lu * 32] >> 4;
            int hlast = hvv * 32 + 31; if (hlast > nHigh - 1) hlast = nHigh - 1;
            int highMax = s_lmeta[ho + hlast] >> 4;
            if (highMax < lowMin) continue;

            int li = lo + lu * 32 + lane;
            int mi = s_lmeta[li];
            int idxi = mi >> 4;
            int rowoff = (mi & 15) * 9;
            float hi = s_lh[li];
            int hbase = ho + hvv * 32;
            float s = 0.0f, c = 0.0f;
#pragma unroll 4
            for (int r = 0; r < 32; r++) {
                int idx = hbase + ((lane + r) & 31);
                int mj = s_lmeta[idx];
                float hj = s_lh[idx];
                if ((mj >> 4) > idxi) {
                    float alpha = tab[rowoff + (mj & 15)];
                    float xv = alpha * (hi - hj);
                    s += fmaxf(xv, 0.0f) + __logf(1.0f + __expf(-fabsf(xv)));
                    c += 1.0f;
                }
            }
            if (prob == 0) { aS0 += s; aC0 += c; }
            else           { aS1 += s; aC1 += c; }
        }

        aS0 = warpSumF(aS0); aC0 = warpSumF(aC0);
        aS1 = warpSumF(aS1); aC1 = warpSumF(aC1);
        if (lane == 0) {
            s_pr[0][w] = aS0; s_pr[1][w] = aC0;
            s_pr[2][w] = aS1; s_pr[3][w] = aC1;
        }
    }
    __syncthreads();
    if (tid == 0) {
        float a = 0.f, bb = 0.f, c = 0.f, d = 0.f;
#pragma unroll
        for (int k = 0; k < NW; k++) {
            a += s_pr[0][k]; bb += s_pr[1][k];
            c += s_pr[2][k]; d  += s_pr[3][k];
        }
        g_pairp[b] = make_float4(a, bb, c, d);
    }

    // ---- 4. wait barrier (usually already flipped), stage, cox ------------
    if (tid == 0) {
        unsigned ph = s_ph;
        while (g_phase == ph) { }
        __threadfence();
    }
    __syncthreads();

#pragma unroll
    for (int k = 0; k < BMAX / T; k++) {
        int j = k * T + tid;
        if (j < B) {
            float4 v = __ldcg(&g_sp[j]);
            s_surv[j] = v.x;
            s_e[j] = make_float2(v.y, v.z);
        } else {
            s_surv[j] = -CUDART_INF_F;
            s_e[j] = make_float2(0.0f, 0.0f);
        }
    }
    __syncthreads();

    {
        const int rg = w & 3, cc = w >> 2;        // 4 row-groups x 4 col-chunks
        const int rbase = b * EPB + rg * 8;
        float si[8], a3[8], a1[8];
#pragma unroll
        for (int k = 0; k < 8; k++) {
            int r = rbase + k;
            si[k] = (r < B) ? s_surv[r] : CUDART_INF_F;
            a3[k] = 0.0f; a1[k] = 0.0f;
        }
        const int cb = cc * 1024 + lane;
#pragma unroll 4
        for (int it = 0; it < 32; it++) {
            int j = cb + it * 32;
            float  pv = s_surv[j];
            float2 pe = s_e[j];
#pragma unroll
            for (int k = 0; k < 8; k++) {
                if (pv >= si[k]) { a3[k] += pe.x; a1[k] += pe.y; }
            }
        }
#pragma unroll
        for (int k = 0; k < 8; k++) {
            a3[k] = warpSumF(a3[k]);
            a1[k] = warpSumF(a1[k]);
            if (lane == 0) {
                s_p3[rg * 8 + k][cc] = a3[k];
                s_p1[rg * 8 + k][cc] = a1[k];
            }
        }
    }
    __syncthreads();

    if (w == 0) {
        int r = b * EPB + lane;
        float c3 = 0.0f, c1 = 0.0f;
        if (r < B) {
            float t3 = s_p3[lane][0] + s_p3[lane][1] + s_p3[lane][2] + s_p3[lane][3];
            float t1 = s_p1[lane][0] + s_p1[lane][1] + s_p1[lane][2] + s_p1[lane][3];
            float cv = cen[r];
            float2 er = s_e[r];
            c3 = cv * __logf(__fdividef(er.x, t3));
            c1 = cv * __logf(__fdividef(er.y, t1));
        }
        c3 = warpSumF(c3);
        c1 = warpSumF(c1);
        if (lane == 0) g_coxp[b] = make_float2(c3, c1);
    }

    // ---- 5. ticket: last block combines in fixed order --------------------
    if (tid == 0) {
        __threadfence();
        int old = atomicAdd(&g_ticket, 1);
        s_last = (old == G - 1) ? 1 : 0;
    }
    __syncthreads();
    if (s_last) {
        if (tid == 0) { g_ticket = 0; __threadfence(); }
        float a0 = 0.f, a1 = 0.f, a2 = 0.f, a3 = 0.f, a4 = 0.f, a5 = 0.f;
        if (tid < G) {
            float2 cp = __ldcg(&g_coxp[tid]);
            float4 pp = __ldcg(&g_pairp[tid]);
            a0 = cp.x; a1 = cp.y;
            a2 = pp.x; a3 = pp.y; a4 = pp.z; a5 = pp.w;
        }
        a0 = warpSumF(a0); a1 = warpSumF(a1); a2 = warpSumF(a2);
        a3 = warpSumF(a3); a4 = warpSumF(a4); a5 = warpSumF(a5);
        if (lane == 0 && w < 4) {
            s_fin[0][w] = a0; s_fin[1][w] = a1; s_fin[2][w] = a2;
            s_fin[3][w] = a3; s_fin[4][w] = a4; s_fin[5][w] = a5;
        }
        __syncthreads();
        if (tid == 0) {
            float s0 = 0.f, s1 = 0.f, s2 = 0.f, s3 = 0.f, s4 = 0.f, s5 = 0.f;
#pragma unroll
            for (int k = 0; k < 4; k++) {
                s0 += s_fin[0][k]; s1 += s_fin[1][k]; s2 += s_fin[2][k];
                s3 += s_fin[3][k]; s4 += s_fin[4][k]; s5 += s_fin[5][k];
            }
            float invB = 1.0f / (float)B;
            float loss3d = -s0 * invB;
            float loss1d = -s1 * invB;
            float lgg = (s3 > 0.5f) ? (s2 / s3) : 0.0f;
            float hgg = (s5 > 0.5f) ? (s4 / s5) : 0.0f;
            float losscli = lgg + hgg;
            float v0 = vars[0], v2 = vars[2], v3 = vars[3];
            out[0] = 0.5f * loss3d / (v0 * v0) + logf(v0)
                   + 0.5f * loss1d / (v2 * v2) + logf(v2)
                   + 0.5f * losscli / (v3 * v3) + logf(v3);
        }
    }
}

extern "C" void kernel_launch(void* const* d_in, const int* in_sizes, int n_in,
                              void* d_out, int out_size) {
    const float* h3     = (const float*)d_in[0];
    const float* h1     = (const float*)d_in[1];
    const float* surv   = (const float*)d_in[2];
    const float* censor = (const float*)d_in[3];
    const float* vars   = (const float*)d_in[4];
    const float* beta1  = (const float*)d_in[5];
    const float* beta2  = (const float*)d_in[6];
    const int*   age    = (const int*)d_in[7];
    const int*   grade  = (const int*)d_in[8];
    int B = in_sizes[0];

    size_t smem = (size_t)(3 * BMAX) * sizeof(float)
                + (size_t)LISTPAD * (sizeof(int) + sizeof(float));   // ~82KB
    cudaFuncSetAttribute(fused_kernel, cudaFuncAttributeMaxDynamicSharedMemorySize,
                         (int)smem);
    fused_kernel<<<G, T, smem>>>(h3, h1, surv, censor, vars, beta1, beta2,
                                 age, grade, (float*)d_out, B);
}

// round 9
// speedup vs baseline: 1.0843x; 1.0843x over previous
#include <cuda_runtime.h>
#include <math_constants.h>

// ---------------------------------------------------------------------------
// MultiTaskLossWrapper — single launch, one hidden grid barrier, T=1024.
// Schedule per block:
//   1. warp 0 produces exp() for its own 32 elements into g_sp, arrives
//   2. build the 4 pair lists locally (age/grade/h3 only)
//   3. run its share of pair-rank units (hides the barrier wait)
//   4. wait barrier, stage g_sp -> smem, Cox sweep (32 warps)
//   5. last block (atomic ticket) combines all partials in fixed order
// No fp atomics; deterministic; replay-safe.
// Inputs: 0 hazard3d f32[B], 1 hazard1d f32[B], 2 survtime f32[B],
//         3 censor f32[B], 4 vars_ f32[4], 5 beta1, 6 beta2,
//         7 age i32[B], 8 grade i32[B].  Output: f32[1]
// ---------------------------------------------------------------------------

#define G 128
#define T 1024
#define NW 32
#define TOTW (G * NW)
#define BMAX 4096
#define EPB 32
#define NK 4                   // elems per thread for list building
#define LISTPAD (BMAX + 128)

__constant__ float c_risk_table[9] = {1.0f, 1.0f, 0.91f, 1.12f, 1.71f,
                                      2.41f, 3.27f, 5.18f, 8.44f};

__device__ float4 g_sp[BMAX];          // (surv, exp(h3), exp(h1), censor)
__device__ float2 g_coxp[G];
__device__ float4 g_pairp[G];
__device__ int               g_arr = 0;       // barrier arrive counter
__device__ volatile unsigned g_phase = 0;     // monotone across replays
__device__ int               g_ticket = 0;    // finisher resets

__device__ __forceinline__ float warpSumF(float v) {
#pragma unroll
    for (int o = 16; o; o >>= 1) v += __shfl_xor_sync(0xffffffffu, v, o);
    return v;
}

__global__ void __launch_bounds__(T)
fused_kernel(const float* __restrict__ h3, const float* __restrict__ h1,
             const float* __restrict__ surv, const float* __restrict__ cen,
             const float* __restrict__ vars,
             const float* __restrict__ b1p, const float* __restrict__ b2p,
             const int* __restrict__ age, const int* __restrict__ grade,
             float* __restrict__ out, int B) {
    extern __shared__ float sm[];
    float*  s_surv  = sm;                                  // [BMAX]
    float2* s_e     = (float2*)(sm + BMAX);                // [BMAX]
    int*    s_lmeta = (int*)(sm + 3 * BMAX);               // [LISTPAD]
    float*  s_lh    = (float*)(sm + 3 * BMAX + LISTPAD);   // [LISTPAD]

    __shared__ int      s_gc[4][NW * NK];
    __shared__ int      s_tot[4], s_off[5];
    __shared__ float    tabL[81], tabH[81];
    __shared__ float    s_p3[EPB][8], s_p1[EPB][8];
    __shared__ float    s_pr[4][NW];
    __shared__ float    s_fin[6][4];
    __shared__ unsigned s_ph;
    __shared__ int      s_last;

    const int b = blockIdx.x, tid = threadIdx.x;
    const int w = tid >> 5, lane = tid & 31;

    if (tid == 0) s_ph = g_phase;    // capture phase before any arrive

    // ---- 1. produce our 32 elements of g_sp, arrive (non-blocking) --------
    if (w == 0) {
        int e = b * EPB + lane;
        if (e < B) {
            g_sp[e] = make_float4(surv[e], __expf(h3[e]), __expf(h1[e]), cen[e]);
        }
        __syncwarp();
        if (lane == 0) {
            __threadfence();
            unsigned ph = s_ph;
            if (atomicAdd(&g_arr, 1) == G - 1) {
                g_arr = 0;
                __threadfence();
                g_phase = ph + 1;
            }
        }
    } else if (tid >= 32 && tid < 194) {
        int q = tid - 32;
        bool isL = q < 81;
        int i = isL ? q : q - 81;
        float bb = isL ? *b1p : *b2p;
        float d = (c_risk_table[i % 9] - c_risk_table[i / 9]) * 0.125f;
        float al = __fdividef(d, 1.0f + __expf(-bb * d));
        if (isL) tabL[i] = al; else tabH[i] = al;
    }

    // ---- 2. build pair lists locally --------------------------------------
    unsigned mlpack = 0u, bkpack = 0u;
    float hv[NK];
    {
        int a8[NK], g8[NK];
#pragma unroll
        for (int k = 0; k < NK; k++) {
            int e = w * (NK * 32) + k * 32 + lane;
            bool valid = (e < B);
            a8[k] = valid ? age[e]   : -1;
            g8[k] = valid ? grade[e] : -1;
            hv[k] = valid ? h3[e]    : 0.0f;
        }
#pragma unroll
        for (int k = 0; k < NK; k++) {
            int a_ = a8[k], g_ = g8[k];
            int ml = -1;
            if (g_ == 0)                 ml = (a_ < 40) ? 0 : 1;
            else if (g_ == 1 || g_ == 2) ml = (a_ < 65) ? 2 : 3;
            int bkt = a_ / 10; bkt = bkt < 0 ? 0 : (bkt > 8 ? 8 : bkt);
            mlpack |= (unsigned)(ml + 1) << (3 * k);
            bkpack |= (unsigned)bkt << (4 * k);
#pragma unroll
            for (int l = 0; l < 4; l++) {
                unsigned mk = __ballot_sync(0xffffffffu, ml == l);
                if (lane == 0) s_gc[l][w * NK + k] = __popc(mk);
            }
        }
    }
    __syncthreads();

    if (w < 4) {     // warp l: exclusive scan of 128 group counts
        int l = w;
        int g0 = lane * 4;
        int v0 = s_gc[l][g0], v1 = s_gc[l][g0 + 1];
        int v2 = s_gc[l][g0 + 2], v3 = s_gc[l][g0 + 3];
        int ls = v0 + v1 + v2 + v3;
        int x = ls;
#pragma unroll
        for (int o = 1; o < 32; o <<= 1) {
            int y = __shfl_up_sync(0xffffffffu, x, o);
            if (lane >= o) x += y;
        }
        int base = x - ls;
        s_gc[l][g0]     = base;
        s_gc[l][g0 + 1] = base + v0;
        s_gc[l][g0 + 2] = base + v0 + v1;
        s_gc[l][g0 + 3] = base + v0 + v1 + v2;
        if (lane == 31) s_tot[l] = x;
    }
    __syncthreads();
    if (tid == 0) {
        int o = 0;
#pragma unroll
        for (int l = 0; l < 4; l++) { s_off[l] = o; o += (s_tot[l] + 31) & ~31; }
        s_off[4] = o;
    }
    __syncthreads();

#pragma unroll
    for (int k = 0; k < NK; k++) {
        int ml = (int)((mlpack >> (3 * k)) & 7u) - 1;
        unsigned mymask = 0u;
#pragma unroll
        for (int l = 0; l < 4; l++) {
            unsigned mk = __ballot_sync(0xffffffffu, ml == l);
            if (ml == l) mymask = mk;
        }
        if (ml >= 0) {
            int e = w * (NK * 32) + k * 32 + lane;
            int bkt = (int)((bkpack >> (4 * k)) & 15u);
            int pos = s_off[ml] + s_gc[ml][w * NK + k]
                    + __popc(mymask & ((1u << lane) - 1u));
            s_lmeta[pos] = (e << 4) | bkt;
            s_lh[pos] = hv[k];
        }
    }
#pragma unroll
    for (int l = 0; l < 4; l++) {
        int sent = (l == 0 || l == 2) ? 0x7FFFFFF0 : -16;
        for (int i = s_off[l] + s_tot[l] + tid; i < s_off[l + 1]; i += T) {
            s_lmeta[i] = sent; s_lh[i] = 0.0f;
        }
    }
    __syncthreads();   // lists + tables complete

    // ---- 3. pair phase (hides the barrier wait) ---------------------------
    {
        const int n0 = s_tot[0], n1 = s_tot[1], n2 = s_tot[2], n3 = s_tot[3];
        const int uL = (n0 + 31) >> 5, vL = (n1 + 31) >> 5;
        const int uH = (n2 + 31) >> 5, vH = (n3 + 31) >> 5;
        const int NTL = uL * vL, NT = NTL + uH * vH;
        float aS0 = 0.f, aC0 = 0.f, aS1 = 0.f, aC1 = 0.f;
        const int gw = b * NW + w;

        for (int t = gw; t < NT; t += TOTW) {
            int prob, lu, hvv, lo, ho, nHigh;
            const float* tab;
            if (t < NTL) {
                prob = 0; lu = t / vL; hvv = t - lu * vL;
                lo = s_off[0]; ho = s_off[1]; nHigh = n1; tab = tabL;
            } else {
                int tt = t - NTL;
                prob = 1; lu = tt / vH; hvv = tt - lu * vH;
                lo = s_off[2]; ho = s_off[3]; nHigh = n3; tab = tabH;
            }
            int lowMin = s_lmeta[lo + lu * 32] >> 4;
            int hlast = hvv * 32 + 31; if (hlast > nHigh - 1) hlast = nHigh - 1;
            int highMax = s_lmeta[ho + hlast] >> 4;
            if (highMax < lowMin) continue;

            int li = lo + lu * 32 + lane;
            int mi = s_lmeta[li];
            int idxi = mi >> 4;
            int rowoff = (mi & 15) * 9;
            float hi = s_lh[li];
            int hbase = ho + hvv * 32;
            float s = 0.0f, c = 0.0f;
#pragma unroll 4
            for (int r = 0; r < 32; r++) {
                int idx = hbase + ((lane + r) & 31);
                int mj = s_lmeta[idx];
                float hj = s_lh[idx];
                if ((mj >> 4) > idxi) {
                    float alpha = tab[rowoff + (mj & 15)];
                    float xv = alpha * (hi - hj);
                    s += fmaxf(xv, 0.0f) + __logf(1.0f + __expf(-fabsf(xv)));
                    c += 1.0f;
                }
            }
            if (prob == 0) { aS0 += s; aC0 += c; }
            else           { aS1 += s; aC1 += c; }
        }

        aS0 = warpSumF(aS0); aC0 = warpSumF(aC0);
        aS1 = warpSumF(aS1); aC1 = warpSumF(aC1);
        if (lane == 0) {
            s_pr[0][w] = aS0; s_pr[1][w] = aC0;
            s_pr[2][w] = aS1; s_pr[3][w] = aC1;
        }
    }
    __syncthreads();
    if (tid == 0) {
        float a = 0.f, bb = 0.f, c = 0.f, d = 0.f;
#pragma unroll
        for (int k = 0; k < NW; k++) {
            a += s_pr[0][k]; bb += s_pr[1][k];
            c += s_pr[2][k]; d  += s_pr[3][k];
        }
        g_pairp[b] = make_float4(a, bb, c, d);
    }

    // ---- 4. wait barrier (usually already flipped), stage, cox ------------
    if (tid == 0) {
        unsigned ph = s_ph;
        while (g_phase == ph) { }
        __threadfence();
    }
    __syncthreads();

#pragma unroll
    for (int k = 0; k < BMAX / T; k++) {
        int j = k * T + tid;
        if (j < B) {
            float4 v = __ldcg(&g_sp[j]);
            s_surv[j] = v.x;
            s_e[j] = make_float2(v.y, v.z);
        } else {
            s_surv[j] = -CUDART_INF_F;
            s_e[j] = make_float2(0.0f, 0.0f);
        }
    }
    __syncthreads();

    {
        const int rg = w & 3, cc = w >> 2;      // 4 row-groups x 8 col-chunks
        const int rbase = b * EPB + rg * 8;
        float si[8], a3[8], a1[8];
#pragma unroll
        for (int k = 0; k < 8; k++) {
            int r = rbase + k;
            si[k] = (r < B) ? s_surv[r] : CUDART_INF_F;
            a3[k] = 0.0f; a1[k] = 0.0f;
        }
        const int cb = cc * 512 + lane;
#pragma unroll 4
        for (int it = 0; it < 16; it++) {
            int j = cb + it * 32;
            float  pv = s_surv[j];
            float2 pe = s_e[j];
#pragma unroll
            for (int k = 0; k < 8; k++) {
                if (pv >= si[k]) { a3[k] += pe.x; a1[k] += pe.y; }
            }
        }
#pragma unroll
        for (int k = 0; k < 8; k++) {
            a3[k] = warpSumF(a3[k]);
            a1[k] = warpSumF(a1[k]);
            if (lane == 0) {
                s_p3[rg * 8 + k][cc] = a3[k];
                s_p1[rg * 8 + k][cc] = a1[k];
            }
        }
    }
    __syncthreads();

    if (w == 0) {
        int r = b * EPB + lane;
        float c3 = 0.0f, c1 = 0.0f;
        if (r < B) {
            float t3 = 0.0f, t1 = 0.0f;
#pragma unroll
            for (int c = 0; c < 8; c++) { t3 += s_p3[lane][c]; t1 += s_p1[lane][c]; }
            float cv = cen[r];
            float2 er = s_e[r];
            c3 = cv * __logf(__fdividef(er.x, t3));
            c1 = cv * __logf(__fdividef(er.y, t1));
        }
        c3 = warpSumF(c3);
        c1 = warpSumF(c1);
        if (lane == 0) g_coxp[b] = make_float2(c3, c1);
    }

    // ---- 5. ticket: last block combines in fixed order --------------------
    if (tid == 0) {
        __threadfence();
        int old = atomicAdd(&g_ticket, 1);
        s_last = (old == G - 1) ? 1 : 0;
    }
    __syncthreads();
    if (s_last) {
        if (tid == 0) { g_ticket = 0; __threadfence(); }
        float a0 = 0.f, a1 = 0.f, a2 = 0.f, a3 = 0.f, a4 = 0.f, a5 = 0.f;
        if (tid < G) {
            float2 cp = __ldcg(&g_coxp[tid]);
            float4 pp = __ldcg(&g_pairp[tid]);
            a0 = cp.x; a1 = cp.y;
            a2 = pp.x; a3 = pp.y; a4 = pp.z; a5 = pp.w;
        }
        a0 = warpSumF(a0); a1 = warpSumF(a1); a2 = warpSumF(a2);
        a3 = warpSumF(a3); a4 = warpSumF(a4); a5 = warpSumF(a5);
        if (lane == 0 && w < 4) {
            s_fin[0][w] = a0; s_fin[1][w] = a1; s_fin[2][w] = a2;
            s_fin[3][w] = a3; s_fin[4][w] = a4; s_fin[5][w] = a5;
        }
        __syncthreads();
        if (tid == 0) {
            float s0 = 0.f, s1 = 0.f, s2 = 0.f, s3 = 0.f, s4 = 0.f, s5 = 0.f;
#pragma unroll
            for (int k = 0; k < 4; k++) {
                s0 += s_fin[0][k]; s1 += s_fin[1][k]; s2 += s_fin[2][k];
                s3 += s_fin[3][k]; s4 += s_fin[4][k]; s5 += s_fin[5][k];
            }
            float invB = 1.0f / (float)B;
            float loss3d = -s0 * invB;
            float loss1d = -s1 * invB;
            float lgg = (s3 > 0.5f) ? (s2 / s3) : 0.0f;
            float hgg = (s5 > 0.5f) ? (s4 / s5) : 0.0f;
            float losscli = lgg + hgg;
            float v0 = vars[0], v2 = vars[2], v3 = vars[3];
            out[0] = 0.5f * loss3d / (v0 * v0) + logf(v0)
                   + 0.5f * loss1d / (v2 * v2) + logf(v2)
                   + 0.5f * losscli / (v3 * v3) + logf(v3);
        }
    }
}

extern "C" void kernel_launch(void* const* d_in, const int* in_sizes, int n_in,
                              void* d_out, int out_size) {
    const float* h3     = (const float*)d_in[0];
    const float* h1     = (const float*)d_in[1];
    const float* surv   = (const float*)d_in[2];
    const float* censor = (const float*)d_in[3];
    const float* vars   = (const float*)d_in[4];
    const float* beta1  = (const float*)d_in[5];
    const float* beta2  = (const float*)d_in[6];
    const int*   age    = (const int*)d_in[7];
    const int*   grade  = (const int*)d_in[8];
    int B = in_sizes[0];

    size_t smem = (size_t)(3 * BMAX) * sizeof(float)
                + (size_t)LISTPAD * (sizeof(int) + sizeof(float));   // ~82KB
    cudaFuncSetAttribute(fused_kernel, cudaFuncAttributeMaxDynamicSharedMemorySize,
                         (int)smem);
    fused_kernel<<<G, T, smem>>>(h3, h1, surv, censor, vars, beta1, beta2,
                                 age, grade, (float*)d_out, B);
}

// round 10
// speedup vs baseline: 1.2162x; 1.1216x over previous
#include <cuda_runtime.h>
#include <math_constants.h>

// ---------------------------------------------------------------------------
// MultiTaskLossWrapper — barrier-free, fully block-local, G=148.
// Each block: loads all inputs once (exp inline into float4 smem tile),
// builds the 4 pair lists locally (deterministic ballot+scan), runs its
// share of pair-rank tiles, computes Cox for its 28 rows from the smem
// tile, writes partials; last block (atomic ticket) combines in fixed
// order. No grid barrier, no co-residency requirement, no fp atomics.
// Inputs: 0 hazard3d f32[B], 1 hazard1d f32[B], 2 survtime f32[B],
//         3 censor f32[B], 4 vars_ f32[4], 5 beta1, 6 beta2,
//         7 age i32[B], 8 grade i32[B].  Output: f32[1]
// ---------------------------------------------------------------------------

#define G 148
#define T 1024
#define NW 32
#define TOTW (G * NW)
#define BMAX 4096
#define EPB 28                 // rows per block (148*28 >= 4096)
#define NROW 7                 // rows per warp (4 row-groups * 7)
#define NK 4                   // elements per thread (BMAX / T)
#define LISTPAD (BMAX + 128)

__constant__ float c_risk_table[9] = {1.0f, 1.0f, 0.91f, 1.12f, 1.71f,
                                      2.41f, 3.27f, 5.18f, 8.44f};

__device__ float2 g_coxp[G];
__device__ float4 g_pairp[G];
__device__ int    g_ticket = 0;    // finisher resets -> replay-safe

__device__ __forceinline__ float warpSumF(float v) {
#pragma unroll
    for (int o = 16; o; o >>= 1) v += __shfl_xor_sync(0xffffffffu, v, o);
    return v;
}

__global__ void __launch_bounds__(T)
fused_kernel(const float* __restrict__ h3, const float* __restrict__ h1,
             const float* __restrict__ surv, const float* __restrict__ cen,
             const float* __restrict__ vars,
             const float* __restrict__ b1p, const float* __restrict__ b2p,
             const int* __restrict__ age, const int* __restrict__ grade,
             float* __restrict__ out, int B) {
    extern __shared__ float sm[];
    float4* s_sp    = (float4*)sm;                         // [BMAX] (surv,e3,e1,0)
    int*    s_lmeta = (int*)(sm + 4 * BMAX);               // [LISTPAD]
    float*  s_lh    = (float*)(s_lmeta + LISTPAD);         // [LISTPAD]

    __shared__ int   s_gc[4][128];       // per-(list, 32-elem group) counts->bases
    __shared__ int   s_tot[4], s_off[5];
    __shared__ float tabL[81], tabH[81];
    __shared__ float s_p3[EPB][8], s_p1[EPB][8];
    __shared__ float s_pr[4][NW];
    __shared__ float s_fin[6][5];
    __shared__ int   s_last;

    const int b = blockIdx.x, tid = threadIdx.x;
    const int w = tid >> 5, lane = tid & 31;

    // ---- alpha tables ------------------------------------------------------
    if (tid < 162) {
        bool isL = tid < 81;
        int i = isL ? tid : tid - 81;
        float bb = isL ? *b1p : *b2p;
        float d = (c_risk_table[i % 9] - c_risk_table[i / 9]) * 0.125f;
        float al = __fdividef(d, 1.0f + __expf(-bb * d));
        if (isL) tabL[i] = al; else tabH[i] = al;
    }

    // ---- phase 1: load everything once; exp inline; list ballots ----------
    unsigned mlpack = 0u, bkpack = 0u;
    unsigned mymask[NK];
    float    hv[NK];
#pragma unroll
    for (int k = 0; k < NK; k++) {
        int e = k * T + tid;                 // element; group = e>>5 = k*32+w
        bool valid = (e < B);
        float sv = -CUDART_INF_F, e3v = 0.0f, e1v = 0.0f;
        int a_ = -1, g_ = -1;
        hv[k] = 0.0f;
        if (valid) {
            sv = surv[e];
            float v3 = h3[e], v1 = h1[e];
            e3v = __expf(v3);
            e1v = __expf(v1);
            hv[k] = v3;
            a_ = age[e];
            g_ = grade[e];
        }
        s_sp[e] = make_float4(sv, e3v, e1v, 0.0f);
        int ml = -1;
        if (g_ == 0)                 ml = (a_ < 40) ? 0 : 1;
        else if (g_ == 1 || g_ == 2) ml = (a_ < 65) ? 2 : 3;
        int bkt = a_ / 10; bkt = bkt < 0 ? 0 : (bkt > 8 ? 8 : bkt);
        mlpack |= (unsigned)(ml + 1) << (3 * k);
        bkpack |= (unsigned)bkt << (4 * k);
        mymask[k] = 0u;
#pragma unroll
        for (int l = 0; l < 4; l++) {
            unsigned mk = __ballot_sync(0xffffffffu, ml == l);
            if (ml == l) mymask[k] = mk;
            if (lane == 0) s_gc[l][k * 32 + w] = __popc(mk);
        }
    }
    __syncthreads();

    // ---- phase 2: exclusive scan of 128 group counts (warp l = list l) ----
    if (w < 4) {
        int l = w;
        int g0 = lane * 4;
        int v0 = s_gc[l][g0], v1 = s_gc[l][g0 + 1];
        int v2 = s_gc[l][g0 + 2], v3 = s_gc[l][g0 + 3];
        int ls = v0 + v1 + v2 + v3;
        int x = ls;
#pragma unroll
        for (int o = 1; o < 32; o <<= 1) {
            int y = __shfl_up_sync(0xffffffffu, x, o);
            if (lane >= o) x += y;
        }
        int base = x - ls;
        s_gc[l][g0]     = base;
        s_gc[l][g0 + 1] = base + v0;
        s_gc[l][g0 + 2] = base + v0 + v1;
        s_gc[l][g0 + 3] = base + v0 + v1 + v2;
        if (lane == 31) s_tot[l] = x;
    }
    __syncthreads();
    if (tid == 0) {
        int o = 0;
#pragma unroll
        for (int l = 0; l < 4; l++) { s_off[l] = o; o += (s_tot[l] + 31) & ~31; }
        s_off[4] = o;
    }
    __syncthreads();

    // ---- phase 3: scatter (reuse captured masks) + sentinel pads ----------
#pragma unroll
    for (int k = 0; k < NK; k++) {
        int ml = (int)((mlpack >> (3 * k)) & 7u) - 1;
        if (ml >= 0) {
            int e = k * T + tid;
            int bkt = (int)((bkpack >> (4 * k)) & 15u);
            int pos = s_off[ml] + s_gc[ml][k * 32 + w]
                    + __popc(mymask[k] & ((1u << lane) - 1u));
            s_lmeta[pos] = (e << 4) | bkt;
            s_lh[pos] = hv[k];
        }
    }
#pragma unroll
    for (int l = 0; l < 4; l++) {
        int sent = (l == 0 || l == 2) ? 0x7FFFFFF0 : -16;
        for (int i = s_off[l] + s_tot[l] + tid; i < s_off[l + 1]; i += T) {
            s_lmeta[i] = sent; s_lh[i] = 0.0f;
        }
    }
    __syncthreads();   // lists + tables + s_sp complete

    // ---- phase 4: pair-rank tiles (broadcast-high inner loop) -------------
    {
        const int n0 = s_tot[0], n1 = s_tot[1], n2 = s_tot[2], n3 = s_tot[3];
        const int uL = (n0 + 31) >> 5, vL = (n1 + 31) >> 5;
        const int uH = (n2 + 31) >> 5, vH = (n3 + 31) >> 5;
        const int NTL = uL * vL, NT = NTL + uH * vH;
        float aS0 = 0.f, aC0 = 0.f, aS1 = 0.f, aC1 = 0.f;
        const int gw = b * NW + w;

        for (int t = gw; t < NT; t += TOTW) {
            int prob, lu, hvv, lo, ho, nHigh;
            const float* tab;
            if (t < NTL) {
                prob = 0; lu = t / vL; hvv = t - lu * vL;
                lo = s_off[0]; ho = s_off[1]; nHigh = n1; tab = tabL;
            } else {
                int tt = t - NTL;
                prob = 1; lu = tt / vH; hvv = tt - lu * vH;
                lo = s_off[2]; ho = s_off[3]; nHigh = n3; tab = tabH;
            }
            int lowMin = s_lmeta[lo + lu * 32] >> 4;
            int hlast = hvv * 32 + 31; if (hlast > nHigh - 1) hlast = nHigh - 1;
            int highMax = s_lmeta[ho + hlast] >> 4;
            if (highMax < lowMin) continue;

            int li = lo + lu * 32 + lane;     // lane owns a LOW element
            int mi = s_lmeta[li];
            int idxi = mi >> 4;
            int rowoff = (mi & 15) * 9;
            float hi = s_lh[li];
            int hbase = ho + hvv * 32;
            float s = 0.0f, c = 0.0f;
#pragma unroll 4
            for (int jj = 0; jj < 32; jj++) {
                int   mj = s_lmeta[hbase + jj];   // uniform (broadcast)
                float hj = s_lh[hbase + jj];      // uniform (broadcast)
                if ((mj >> 4) > idxi) {
                    float alpha = tab[rowoff + (mj & 15)];  // conflict-free
                    float xv = alpha * (hi - hj);
                    s += fmaxf(xv, 0.0f) + __logf(1.0f + __expf(-fabsf(xv)));
                    c += 1.0f;
                }
            }
            if (prob == 0) { aS0 += s; aC0 += c; }
            else           { aS1 += s; aC1 += c; }
        }

        aS0 = warpSumF(aS0); aC0 = warpSumF(aC0);
        aS1 = warpSumF(aS1); aC1 = warpSumF(aC1);
        if (lane == 0) {
            s_pr[0][w] = aS0; s_pr[1][w] = aC0;
            s_pr[2][w] = aS1; s_pr[3][w] = aC1;
        }
    }

    // ---- phase 5: cox sweep straight from the smem tile -------------------
    {
        const int rg = w & 3, cc = w >> 2;     // 4 row-groups x 8 col-chunks
        const int rbase = b * EPB + rg * NROW;
        float si[NROW], a3[NROW], a1[NROW];
#pragma unroll
        for (int k = 0; k < NROW; k++) {
            int r = rbase + k;
            si[k] = (r < B) ? s_sp[r].x : CUDART_INF_F;
            a3[k] = 0.0f; a1[k] = 0.0f;
        }
        const int cb = cc * 512 + lane;
#pragma unroll 4
        for (int it = 0; it < 16; it++) {
            float4 p = s_sp[cb + it * 32];     // single LDS.128
#pragma unroll
            for (int k = 0; k < NROW; k++) {
                if (p.x >= si[k]) { a3[k] += p.y; a1[k] += p.z; }
            }
        }
#pragma unroll
        for (int k = 0; k < NROW; k++) {
            a3[k] = warpSumF(a3[k]);
            a1[k] = warpSumF(a1[k]);
            if (lane == 0) {
                s_p3[rg * NROW + k][cc] = a3[k];
                s_p1[rg * NROW + k][cc] = a1[k];
            }
        }
    }
    __syncthreads();

    if (w == 0) {
        float c3 = 0.0f, c1 = 0.0f;
        if (lane < EPB) {
            int r = b * EPB + lane;
            if (r < B) {
                float t3 = 0.0f, t1 = 0.0f;
#pragma unroll
                for (int c = 0; c < 8; c++) { t3 += s_p3[lane][c]; t1 += s_p1[lane][c]; }
                float cv = cen[r];
                float4 q = s_sp[r];
                c3 = cv * __logf(__fdividef(q.y, t3));
                c1 = cv * __logf(__fdividef(q.z, t1));
            }
        }
        c3 = warpSumF(c3);
        c1 = warpSumF(c1);
        if (lane == 0) g_coxp[b] = make_float2(c3, c1);
    } else if (w == 1 && lane == 0) {
        float a = 0.f, bb = 0.f, c = 0.f, d = 0.f;
#pragma unroll
        for (int k = 0; k < NW; k++) {
            a += s_pr[0][k]; bb += s_pr[1][k];
            c += s_pr[2][k]; d  += s_pr[3][k];
        }
        g_pairp[b] = make_float4(a, bb, c, d);
    }

    // ---- phase 6: ticket — last block combines in fixed order -------------
    if (tid == 0) {
        __threadfence();
        int old = atomicAdd(&g_ticket, 1);
        s_last = (old == G - 1) ? 1 : 0;
    }
    __syncthreads();
    if (s_last) {
        if (tid == 0) { g_ticket = 0; __threadfence(); }
        float a0 = 0.f, a1 = 0.f, a2 = 0.f, a3 = 0.f, a4 = 0.f, a5 = 0.f;
        if (tid < G) {
            float2 cp = __ldcg(&g_coxp[tid]);
            float4 pp = __ldcg(&g_pairp[tid]);
            a0 = cp.x; a1 = cp.y;
            a2 = pp.x; a3 = pp.y; a4 = pp.z; a5 = pp.w;
        }
        a0 = warpSumF(a0); a1 = warpSumF(a1); a2 = warpSumF(a2);
        a3 = warpSumF(a3); a4 = warpSumF(a4); a5 = warpSumF(a5);
        if (lane == 0 && w < 5) {
            s_fin[0][w] = a0; s_fin[1][w] = a1; s_fin[2][w] = a2;
            s_fin[3][w] = a3; s_fin[4][w] = a4; s_fin[5][w] = a5;
        }
        __syncthreads();
        if (tid == 0) {
            float s0 = 0.f, s1 = 0.f, s2 = 0.f, s3 = 0.f, s4 = 0.f, s5 = 0.f;
#pragma unroll
            for (int k = 0; k < 5; k++) {
                s0 += s_fin[0][k]; s1 += s_fin[1][k]; s2 += s_fin[2][k];
                s3 += s_fin[3][k]; s4 += s_fin[4][k]; s5 += s_fin[5][k];
            }
            float invB = 1.0f / (float)B;
            float loss3d = -s0 * invB;
            float loss1d = -s1 * invB;
            float lgg = (s3 > 0.5f) ? (s2 / s3) : 0.0f;
            float hgg = (s5 > 0.5f) ? (s4 / s5) : 0.0f;
            float losscli = lgg + hgg;
            float v0 = vars[0], v2 = vars[2], v3 = vars[3];
            out[0] = 0.5f * loss3d / (v0 * v0) + logf(v0)
                   + 0.5f * loss1d / (v2 * v2) + logf(v2)
                   + 0.5f * losscli / (v3 * v3) + logf(v3);
        }
    }
}

extern "C" void kernel_launch(void* const* d_in, const int* in_sizes, int n_in,
                              void* d_out, int out_size) {
    const float* h3     = (const float*)d_in[0];
    const float* h1     = (const float*)d_in[1];
    const float* surv   = (const float*)d_in[2];
    const float* censor = (const float*)d_in[3];
    const float* vars   = (const float*)d_in[4];
    const float* beta1  = (const float*)d_in[5];
    const float* beta2  = (const float*)d_in[6];
    const int*   age    = (const int*)d_in[7];
    const int*   grade  = (const int*)d_in[8];
    int B = in_sizes[0];

    size_t smem = (size_t)BMAX * sizeof(float4)
                + (size_t)LISTPAD * (sizeof(int) + sizeof(float));   // ~98KB
    cudaFuncSetAttribute(fused_kernel, cudaFuncAttributeMaxDynamicSharedMemorySize,
                         (int)smem);
    fused_kernel<<<G, T, smem>>>(h3, h1, surv, censor, vars, beta1, beta2,
                                 age, grade, (float*)d_out, B);
}